// round 2
// baseline (speedup 1.0000x reference)
#include <cuda_runtime.h>

#define H 4096
#define HH (H * H)                 // 16777216
#define OUT_ACT  0                 // activout[4]
#define OUT_VAL  4                 // valueout[1]
#define OUT_HACT 5                 // hactiv[4096]
#define OUT_HEBB 4101              // hebb_new[H*H]  (float offset 4101 == 1 mod 4)
#define NC       ((HH - 4) / 4 + 1) // 4194303 aligned 16B output chunks

__device__ float g_y[H];           // pre-tanh accumulator
__device__ float g_hact[H];        // aligned copy of hactiv for the hebb kernel

// ---------------------------------------------------------------------------
// Kernel 0: y[j] = bi[j] + sum_k x[k]*Wi[k,j]   (17x4096, tiny)
// ---------------------------------------------------------------------------
__global__ void init_y_kernel(const float* __restrict__ x,
                              const float* __restrict__ Wi,
                              const float* __restrict__ bi) {
    int j = blockIdx.x * blockDim.x + threadIdx.x;
    if (j >= H) return;
    float s = bi[j];
#pragma unroll
    for (int k = 0; k < 17; k++)
        s = fmaf(x[k], Wi[k * H + j], s);
    g_y[j] = s;
}

// ---------------------------------------------------------------------------
// Kernel 1: y[j] += sum_i hidden[i] * (w[i,j] + alpha[i,j]*hebb[i,j])
// Streams 192 MB. w/alpha loaded evict-first (__ldcs) so hebb (64MB) stays
// resident in the 126MB L2 for the hebb_update kernel's re-read.
// grid = (4 col-tiles of 1024 cols, 256 row-chunks of 16 rows) = 1024 blocks
// ---------------------------------------------------------------------------
__global__ void __launch_bounds__(256)
gemv_acc_kernel(const float* __restrict__ hidden,
                const float* __restrict__ w,
                const float* __restrict__ alpha,
                const float* __restrict__ hebb) {
    int j  = (blockIdx.x * 256 + threadIdx.x) * 4;   // column base (float4)
    int r0 = blockIdx.y * 16;                        // row chunk
    float4 acc = make_float4(0.f, 0.f, 0.f, 0.f);
#pragma unroll 4
    for (int i = r0; i < r0 + 16; ++i) {
        float h = __ldg(hidden + i);                 // broadcast within warp
        size_t off = (size_t)i * H + j;
        float4 wv = __ldcs((const float4*)(w + off));      // evict-first
        float4 av = __ldcs((const float4*)(alpha + off));  // evict-first
        float4 hv = *(const float4*)(hebb + off);          // keep in L2
        acc.x = fmaf(h, fmaf(av.x, hv.x, wv.x), acc.x);
        acc.y = fmaf(h, fmaf(av.y, hv.y, wv.y), acc.y);
        acc.z = fmaf(h, fmaf(av.z, hv.z, wv.z), acc.z);
        acc.w = fmaf(h, fmaf(av.w, hv.w, wv.w), acc.w);
    }
    atomicAdd(&g_y[j + 0], acc.x);
    atomicAdd(&g_y[j + 1], acc.y);
    atomicAdd(&g_y[j + 2], acc.z);
    atomicAdd(&g_y[j + 3], acc.w);
}

// ---------------------------------------------------------------------------
// Kernel 2: hactiv = tanh(y); heads (softmax over 4 actions, value); 1 block.
// ---------------------------------------------------------------------------
__inline__ __device__ float warp_sum(float v) {
#pragma unroll
    for (int o = 16; o > 0; o >>= 1)
        v += __shfl_down_sync(0xffffffffu, v, o);
    return v;
}

__global__ void __launch_bounds__(1024)
finalize_kernel(const float* __restrict__ Wo, const float* __restrict__ bo,
                const float* __restrict__ Wv, const float* __restrict__ bv,
                float* __restrict__ out) {
    int t = threadIdx.x;
    float p0 = 0.f, p1 = 0.f, p2 = 0.f, p3 = 0.f, pv = 0.f;
#pragma unroll
    for (int j = t; j < H; j += 1024) {
        float hact = tanhf(g_y[j]);
        out[OUT_HACT + j] = hact;
        g_hact[j] = hact;
        float4 wo = *(const float4*)(Wo + (size_t)j * 4);  // 16B aligned
        p0 = fmaf(hact, wo.x, p0);
        p1 = fmaf(hact, wo.y, p1);
        p2 = fmaf(hact, wo.z, p2);
        p3 = fmaf(hact, wo.w, p3);
        pv = fmaf(hact, Wv[j], pv);
    }
    __shared__ float sh[5][32];
    int lane = t & 31, wid = t >> 5;
    p0 = warp_sum(p0); p1 = warp_sum(p1); p2 = warp_sum(p2);
    p3 = warp_sum(p3); pv = warp_sum(pv);
    if (lane == 0) {
        sh[0][wid] = p0; sh[1][wid] = p1; sh[2][wid] = p2;
        sh[3][wid] = p3; sh[4][wid] = pv;
    }
    __syncthreads();
    if (wid == 0) {
        float v0 = warp_sum(sh[0][lane]);
        float v1 = warp_sum(sh[1][lane]);
        float v2 = warp_sum(sh[2][lane]);
        float v3 = warp_sum(sh[3][lane]);
        float v4 = warp_sum(sh[4][lane]);
        if (lane == 0) {
            float l0 = v0 + bo[0], l1 = v1 + bo[1], l2 = v2 + bo[2], l3 = v3 + bo[3];
            float m = fmaxf(fmaxf(l0, l1), fmaxf(l2, l3));
            float e0 = expf(l0 - m), e1 = expf(l1 - m), e2 = expf(l2 - m), e3 = expf(l3 - m);
            float inv = 1.0f / (e0 + e1 + e2 + e3);
            out[OUT_ACT + 0] = e0 * inv;
            out[OUT_ACT + 1] = e1 * inv;
            out[OUT_ACT + 2] = e2 * inv;
            out[OUT_ACT + 3] = e3 * inv;
            out[OUT_VAL] = v4 + bv[0];
        }
    }
}

// ---------------------------------------------------------------------------
// Kernel 3: hebb_new[i,j] = (1-eta)*hebb[i,j] + eta*hidden[i]*hactiv[j]
// Output region misaligned by 1 float (offset 4101): store OUTPUT-aligned
// float4 chunks covering source k = 3+4q .. 6+4q from two adjacent aligned
// hebb float4 loads (same 128B line -> no extra DRAM). hebb should be an L2
// hit (kept resident by gemv's __ldcs policy). Exactly 4 independent,
// fully-unrolled chunks per thread for MLP. Streaming loads/stores.
// grid = 4096 x 256 -> 1,048,576 threads x 4 chunks = 4,194,304 >= NC
// ---------------------------------------------------------------------------
__global__ void __launch_bounds__(256)
hebb_update_kernel(const float* __restrict__ hebb,
                   const float* __restrict__ hidden,
                   const float* __restrict__ eta,
                   float* __restrict__ out) {
    const long long STRIDE = 4096LL * 256LL;   // 1,048,576 threads
    long long tid = (long long)blockIdx.x * 256 + threadIdx.x;
    float et = eta[0];
    float em = 1.0f - et;
    float* ho = out + OUT_HEBB;
    const float4* hb4 = (const float4*)hebb;

    if (tid == 0) {
        // head k = 0..2 (row 0), tail k = HH-1 (row 4095, col 4095)
#pragma unroll
        for (int k = 0; k < 3; k++)
            ho[k] = fmaf(em, hebb[k], et * hidden[0] * g_hact[k]);
        ho[HH - 1] = fmaf(em, hebb[HH - 1], et * hidden[H - 1] * g_hact[H - 1]);
    }

#pragma unroll
    for (int e = 0; e < 4; e++) {
        long long q = tid + (long long)e * STRIDE;
        bool ok = q < NC;
        long long qc = ok ? q : (NC - 1);

        float4 A = __ldcs(hb4 + qc);       // evict-first: no reuse after this
        float4 B = __ldcs(hb4 + qc + 1);   // same/adjacent 128B line
        float s0 = A.w, s1 = B.x, s2 = B.y, s3 = B.z;

        long long k = 4 * qc + 3;
        int j0 = (int)(k & (H - 1));
        int i0 = (int)(k >> 12);
        float4 r;
        if (j0 != H - 1) {
            // fast path: all 4 elements in the same hebb row
            float hi = __ldg(hidden + i0) * et;
            r.x = fmaf(em, s0, hi * g_hact[j0 + 0]);
            r.y = fmaf(em, s1, hi * g_hact[j0 + 1]);
            r.z = fmaf(em, s2, hi * g_hact[j0 + 2]);
            r.w = fmaf(em, s3, hi * g_hact[j0 + 3]);
        } else {
            // chunk straddles a row boundary (1 per 4096 chunks)
            float src[4] = {s0, s1, s2, s3};
            float rr[4];
#pragma unroll
            for (int u = 0; u < 4; u++) {
                long long kk = k + u;
                int i = (int)(kk >> 12);
                int j = (int)(kk & (H - 1));
                rr[u] = fmaf(em, src[u], et * __ldg(hidden + i) * g_hact[j]);
            }
            r = make_float4(rr[0], rr[1], rr[2], rr[3]);
        }
        if (ok)
            __stcs((float4*)(ho + k), r);  // streaming store, never re-read
    }
}

// ---------------------------------------------------------------------------
// inputs: x, hidden, hebb, Wi, bi, w, alpha, eta, Wo, bo, Wv, bv
// output: activout[4] | valueout[1] | hactiv[4096] | hebb_new[4096*4096]
// ---------------------------------------------------------------------------
extern "C" void kernel_launch(void* const* d_in, const int* in_sizes, int n_in,
                              void* d_out, int out_size) {
    const float* x      = (const float*)d_in[0];
    const float* hidden = (const float*)d_in[1];
    const float* hebb   = (const float*)d_in[2];
    const float* Wi     = (const float*)d_in[3];
    const float* bi     = (const float*)d_in[4];
    const float* w      = (const float*)d_in[5];
    const float* alpha  = (const float*)d_in[6];
    const float* eta    = (const float*)d_in[7];
    const float* Wo     = (const float*)d_in[8];
    const float* bo     = (const float*)d_in[9];
    const float* Wv     = (const float*)d_in[10];
    const float* bv     = (const float*)d_in[11];
    float* out = (float*)d_out;

    init_y_kernel<<<H / 256, 256>>>(x, Wi, bi);
    gemv_acc_kernel<<<dim3(4, 256), 256>>>(hidden, w, alpha, hebb);
    finalize_kernel<<<1, 1024>>>(Wo, bo, Wv, bv, out);
    hebb_update_kernel<<<4096, 256>>>(hebb, hidden, eta, out);
}

// round 3
// speedup vs baseline: 1.0198x; 1.0198x over previous
#include <cuda_runtime.h>
#include <cstdint>

#define H 4096
#define HH (H * H)                  // 16777216
#define OUT_ACT  0                  // activout[4]
#define OUT_VAL  4                  // valueout[1]
#define OUT_HACT 5                  // hactiv[4096]
#define OUT_HEBB 4101               // hebb_new[H*H] (float offset 4101 == 1 mod 4)
#define NC  ((HH - 4) / 4 + 1)      // 4194303 valid output chunks (k = 4q+3)
#define HB4N (HH / 4)               // 4194304 valid float4 indices of hebb

__device__ float  g_y[H];           // pre-tanh accumulator
__device__ float  g_hact[H];        // aligned copy of hactiv
__device__ float4 g_hs4[1023];      // g_hs4[m] = hact[4m+3 .. 4m+6] (shifted view)

// ---- cp.async helpers (LDGSTS path: no outstanding-request cap) -----------
#define CPA16(dst_u32, src) \
    asm volatile("cp.async.cg.shared.global [%0], [%1], 16;" \
                 :: "r"(dst_u32), "l"(src) : "memory")
#define CPCOMMIT() asm volatile("cp.async.commit_group;" ::: "memory")
#define CPWAIT(N)  asm volatile("cp.async.wait_group %0;" :: "n"(N) : "memory")

__device__ __forceinline__ uint32_t smem_u32(const void* p) {
    return (uint32_t)__cvta_generic_to_shared(p);
}

// ---------------------------------------------------------------------------
// Kernel 0: y[j] = bi[j] + sum_k x[k]*Wi[k,j]   (17x4096, tiny)
// ---------------------------------------------------------------------------
__global__ void init_y_kernel(const float* __restrict__ x,
                              const float* __restrict__ Wi,
                              const float* __restrict__ bi) {
    int j = blockIdx.x * blockDim.x + threadIdx.x;
    if (j >= H) return;
    float s = bi[j];
#pragma unroll
    for (int k = 0; k < 17; k++)
        s = fmaf(x[k], Wi[k * H + j], s);
    g_y[j] = s;
}

// ---------------------------------------------------------------------------
// Kernel 1: y[j] += sum_i hidden[i] * (w[i,j] + alpha[i,j]*hebb[i,j])
// Streams 192 MB via a 4-stage per-thread cp.async pipeline. Each thread
// copies exactly the 16B it will consume -> no __syncthreads needed.
// grid = (4 col tiles of 1024 cols, 128 row chunks of 32 rows) = 512 blocks.
// ---------------------------------------------------------------------------
__global__ void __launch_bounds__(256)
gemv_acc_kernel(const float* __restrict__ hidden,
                const float* __restrict__ w,
                const float* __restrict__ alpha,
                const float* __restrict__ hebb) {
    __shared__ float4 sw[4][256], sa[4][256], sh[4][256];  // 48 KB exactly
    int t  = threadIdx.x;
    int j  = (blockIdx.x * 256 + t) * 4;     // column base (float4)
    int r0 = blockIdx.y * 32;                // row chunk base
    uint32_t aw = smem_u32(&sw[0][t]);
    uint32_t aa = smem_u32(&sa[0][t]);
    uint32_t ah = smem_u32(&sh[0][t]);

    // prefetch stages 0..2 (groups 0..2)
#pragma unroll
    for (int s = 0; s < 3; s++) {
        size_t off = (size_t)(r0 + s) * H + j;
        CPA16(aw + s * 4096, w + off);
        CPA16(aa + s * 4096, alpha + off);
        CPA16(ah + s * 4096, hebb + off);
        CPCOMMIT();
    }

    float4 acc = make_float4(0.f, 0.f, 0.f, 0.f);
#pragma unroll 4
    for (int i = 0; i < 32; i++) {
        int s = i & 3;
        CPWAIT(2);                           // group i complete
        float4 wv = sw[s][t];
        float4 av = sa[s][t];
        float4 hv = sh[s][t];
        float  hval = __ldg(hidden + r0 + i);
        acc.x = fmaf(hval, fmaf(av.x, hv.x, wv.x), acc.x);
        acc.y = fmaf(hval, fmaf(av.y, hv.y, wv.y), acc.y);
        acc.z = fmaf(hval, fmaf(av.z, hv.z, wv.z), acc.z);
        acc.w = fmaf(hval, fmaf(av.w, hv.w, wv.w), acc.w);
        int nx = i + 3;
        if (nx < 32) {
            int sn = nx & 3;
            size_t off = (size_t)(r0 + nx) * H + j;
            CPA16(aw + sn * 4096, w + off);
            CPA16(aa + sn * 4096, alpha + off);
            CPA16(ah + sn * 4096, hebb + off);
        }
        CPCOMMIT();                          // keep group counting uniform
    }
    atomicAdd(&g_y[j + 0], acc.x);
    atomicAdd(&g_y[j + 1], acc.y);
    atomicAdd(&g_y[j + 2], acc.z);
    atomicAdd(&g_y[j + 3], acc.w);
}

// ---------------------------------------------------------------------------
// Kernel 2: hactiv = tanh(y); heads; also build shifted float4 view of hactiv.
// ---------------------------------------------------------------------------
__inline__ __device__ float warp_sum(float v) {
#pragma unroll
    for (int o = 16; o > 0; o >>= 1)
        v += __shfl_down_sync(0xffffffffu, v, o);
    return v;
}

__global__ void __launch_bounds__(1024)
finalize_kernel(const float* __restrict__ Wo, const float* __restrict__ bo,
                const float* __restrict__ Wv, const float* __restrict__ bv,
                float* __restrict__ out) {
    int t = threadIdx.x;
    float p0 = 0.f, p1 = 0.f, p2 = 0.f, p3 = 0.f, pv = 0.f;
#pragma unroll
    for (int j = t; j < H; j += 1024) {
        float hact = tanhf(g_y[j]);
        out[OUT_HACT + j] = hact;
        g_hact[j] = hact;
        float4 wo = *(const float4*)(Wo + (size_t)j * 4);
        p0 = fmaf(hact, wo.x, p0);
        p1 = fmaf(hact, wo.y, p1);
        p2 = fmaf(hact, wo.z, p2);
        p3 = fmaf(hact, wo.w, p3);
        pv = fmaf(hact, Wv[j], pv);
    }
    __syncthreads();
    if (t < 1023)   // shifted view: g_hs4[m] = hact[4m+3 .. 4m+6]
        g_hs4[t] = make_float4(g_hact[4 * t + 3], g_hact[4 * t + 4],
                               g_hact[4 * t + 5], g_hact[4 * t + 6]);

    __shared__ float sh[5][32];
    int lane = t & 31, wid = t >> 5;
    p0 = warp_sum(p0); p1 = warp_sum(p1); p2 = warp_sum(p2);
    p3 = warp_sum(p3); pv = warp_sum(pv);
    if (lane == 0) {
        sh[0][wid] = p0; sh[1][wid] = p1; sh[2][wid] = p2;
        sh[3][wid] = p3; sh[4][wid] = pv;
    }
    __syncthreads();
    if (wid == 0) {
        float v0 = warp_sum(sh[0][lane]);
        float v1 = warp_sum(sh[1][lane]);
        float v2 = warp_sum(sh[2][lane]);
        float v3 = warp_sum(sh[3][lane]);
        float v4 = warp_sum(sh[4][lane]);
        if (lane == 0) {
            float l0 = v0 + bo[0], l1 = v1 + bo[1], l2 = v2 + bo[2], l3 = v3 + bo[3];
            float m = fmaxf(fmaxf(l0, l1), fmaxf(l2, l3));
            float e0 = expf(l0 - m), e1 = expf(l1 - m), e2 = expf(l2 - m), e3 = expf(l3 - m);
            float inv = 1.0f / (e0 + e1 + e2 + e3);
            out[OUT_ACT + 0] = e0 * inv;
            out[OUT_ACT + 1] = e1 * inv;
            out[OUT_ACT + 2] = e2 * inv;
            out[OUT_ACT + 3] = e3 * inv;
            out[OUT_VAL] = v4 + bv[0];
        }
    }
}

// ---------------------------------------------------------------------------
// Kernel 3: hebb_new[i,j] = (1-eta)*hebb[i,j] + eta*hidden[i]*hactiv[j]
// Block-cooperative cp.async pipeline: each stage loads 1025 float4s of hebb
// into smem (the +1 covers the 1-float shift), compute reads the shifted
// window from smem, stores aligned float4s to out. 4 stages/block, 2 buffers.
// grid = 1024 blocks x 4 stages x 1024 chunks = 4,194,304 >= NC.
// ---------------------------------------------------------------------------
#define HCH 1024                      // chunks per stage
__global__ void __launch_bounds__(256)
hebb_update_kernel(const float* __restrict__ hebb,
                   const float* __restrict__ hidden,
                   const float* __restrict__ eta,
                   float* __restrict__ out) {
    __shared__ float4 sbuf[2][HCH + 1];            // 32,800 B
    int t = threadIdx.x;
    float et = __ldg(eta);
    float em = 1.0f - et;
    float* ho = out + OUT_HEBB;
    const float4* hb4 = (const float4*)hebb;
    long long base = (long long)blockIdx.x * (4LL * HCH);

    if (blockIdx.x == 0 && t == 0) {
        // head k = 0..2 (row 0), tail k = HH-1 (row 4095, col 4095)
#pragma unroll
        for (int k = 0; k < 3; k++)
            ho[k] = fmaf(em, hebb[k], et * hidden[0] * g_hact[k]);
        ho[HH - 1] = fmaf(em, hebb[HH - 1], et * hidden[H - 1] * g_hact[H - 1]);
    }

    // stage loader: 1025 float4s into sbuf[buf]
    auto load_stage = [&](int stg, int buf) {
        long long q0 = base + (long long)stg * HCH;
#pragma unroll
        for (int u = 0; u < 4; u++) {
            long long qi = q0 + u * 256 + t;
            if (qi > HB4N - 1) qi = HB4N - 1;      // clamp (last block only)
            CPA16(smem_u32(&sbuf[buf][u * 256 + t]), hb4 + qi);
        }
        if (t == 0) {
            long long qi = q0 + HCH;
            if (qi > HB4N - 1) qi = HB4N - 1;
            CPA16(smem_u32(&sbuf[buf][HCH]), hb4 + qi);
        }
        CPCOMMIT();
    };

    // compute stage: 4 chunks per thread
    auto compute_stage = [&](int stg, int buf) {
        long long q0 = base + (long long)stg * HCH;
#pragma unroll
        for (int u = 0; u < 4; u++) {
            int c = u * 256 + t;
            long long q = q0 + c;
            if (q >= NC) continue;
            float4 A = sbuf[buf][c];
            float4 B = sbuf[buf][c + 1];
            float s0 = A.w, s1 = B.x, s2 = B.y, s3 = B.z;
            long long k = 4 * q + 3;
            int i0 = (int)(k >> 12);
            int j0 = (int)(k & (H - 1));
            float4 r;
            if (j0 != H - 1) {
                float hi = __ldg(hidden + i0) * et;
                float4 g = g_hs4[j0 >> 2];          // hact[j0 .. j0+3]
                r.x = fmaf(em, s0, hi * g.x);
                r.y = fmaf(em, s1, hi * g.y);
                r.z = fmaf(em, s2, hi * g.z);
                r.w = fmaf(em, s3, hi * g.w);
            } else {                                // row-boundary chunk
                float src[4] = {s0, s1, s2, s3};
                float rr[4];
#pragma unroll
                for (int e = 0; e < 4; e++) {
                    long long kk = k + e;
                    int i = (int)(kk >> 12);
                    int j = (int)(kk & (H - 1));
                    rr[e] = fmaf(em, src[e], et * __ldg(hidden + i) * g_hact[j]);
                }
                r = make_float4(rr[0], rr[1], rr[2], rr[3]);
            }
            __stcs((float4*)(ho + k), r);           // 16B aligned, streaming
        }
    };

    load_stage(0, 0);
    load_stage(1, 1);
#pragma unroll
    for (int s = 0; s < 4; s++) {
        CPWAIT(1);                 // stage s data landed
        __syncthreads();
        compute_stage(s, s & 1);
        if (s + 2 < 4) {
            __syncthreads();       // everyone done reading buf (s&1)
            load_stage(s + 2, s & 1);
        } else {
            CPCOMMIT();            // keep group counting uniform
        }
    }
}

// ---------------------------------------------------------------------------
// inputs: x, hidden, hebb, Wi, bi, w, alpha, eta, Wo, bo, Wv, bv
// output: activout[4] | valueout[1] | hactiv[4096] | hebb_new[H*H]
// ---------------------------------------------------------------------------
extern "C" void kernel_launch(void* const* d_in, const int* in_sizes, int n_in,
                              void* d_out, int out_size) {
    const float* x      = (const float*)d_in[0];
    const float* hidden = (const float*)d_in[1];
    const float* hebb   = (const float*)d_in[2];
    const float* Wi     = (const float*)d_in[3];
    const float* bi     = (const float*)d_in[4];
    const float* w      = (const float*)d_in[5];
    const float* alpha  = (const float*)d_in[6];
    const float* eta    = (const float*)d_in[7];
    const float* Wo     = (const float*)d_in[8];
    const float* bo     = (const float*)d_in[9];
    const float* Wv     = (const float*)d_in[10];
    const float* bv     = (const float*)d_in[11];
    float* out = (float*)d_out;

    init_y_kernel<<<H / 256, 256>>>(x, Wi, bi);
    gemv_acc_kernel<<<dim3(4, 128), 256>>>(hidden, w, alpha, hebb);
    finalize_kernel<<<1, 1024>>>(Wo, bo, Wv, bv, out);
    hebb_update_kernel<<<1024, 256>>>(hebb, hidden, eta, out);
}

// round 4
// speedup vs baseline: 1.0872x; 1.0661x over previous
#include <cuda_runtime.h>
#include <cstdint>

#define H 4096
#define HH (H * H)                  // 16777216
#define OUT_ACT  0                  // activout[4]
#define OUT_VAL  4                  // valueout[1]
#define OUT_HACT 5                  // hactiv[4096]
#define OUT_HEBB 4101               // hebb_new[H*H] (float offset 4101 == 1 mod 4)
#define NC  ((HH - 4) / 4 + 1)      // 4194303 valid output chunks (k = 4q+3)

__device__ float  g_y[H];           // pre-tanh accumulator
__device__ float  g_hact[H];        // aligned copy of hactiv
__device__ float4 g_hs4[1023];      // g_hs4[m] = hact[4m+3 .. 4m+6] (shifted view)
__device__ float  g_head[5];        // raw head sums: Wo cols 0..3, Wv

// ---------------------------------------------------------------------------
// Kernel 0: y[j] = bi[j] + sum_k x[k]*Wi[k,j]; zero g_head.  (tiny)
// ---------------------------------------------------------------------------
__global__ void init_y_kernel(const float* __restrict__ x,
                              const float* __restrict__ Wi,
                              const float* __restrict__ bi) {
    int j = blockIdx.x * blockDim.x + threadIdx.x;
    if (j < 5) g_head[j] = 0.0f;
    if (j >= H) return;
    float s = bi[j];
#pragma unroll
    for (int k = 0; k < 17; k++)
        s = fmaf(x[k], Wi[k * H + j], s);
    g_y[j] = s;
}

// ---------------------------------------------------------------------------
// Kernel 1: y[j] += sum_i hidden[i] * (w[i,j] + alpha[i,j]*hebb[i,j])
// Streams 192 MB. grid = (4 col-tiles of 1024 cols, 256 row-chunks of 16 rows)
// = 1024 blocks, all resident (~55 warps/SM) for max outstanding LDGs.
// ---------------------------------------------------------------------------
__global__ void __launch_bounds__(256)
gemv_acc_kernel(const float* __restrict__ hidden,
                const float* __restrict__ w,
                const float* __restrict__ alpha,
                const float* __restrict__ hebb) {
    int j  = (blockIdx.x * 256 + threadIdx.x) * 4;   // column base (float4)
    int r0 = blockIdx.y * 16;                        // row chunk
    float4 acc = make_float4(0.f, 0.f, 0.f, 0.f);
#pragma unroll 8
    for (int i = r0; i < r0 + 16; ++i) {
        float h = __ldg(hidden + i);                 // broadcast within warp
        size_t off = (size_t)i * H + j;
        float4 wv = *(const float4*)(w + off);
        float4 av = *(const float4*)(alpha + off);
        float4 hv = *(const float4*)(hebb + off);
        acc.x = fmaf(h, fmaf(av.x, hv.x, wv.x), acc.x);
        acc.y = fmaf(h, fmaf(av.y, hv.y, wv.y), acc.y);
        acc.z = fmaf(h, fmaf(av.z, hv.z, wv.z), acc.z);
        acc.w = fmaf(h, fmaf(av.w, hv.w, wv.w), acc.w);
    }
    atomicAdd(&g_y[j + 0], acc.x);
    atomicAdd(&g_y[j + 1], acc.y);
    atomicAdd(&g_y[j + 2], acc.z);
    atomicAdd(&g_y[j + 3], acc.w);
}

// ---------------------------------------------------------------------------
// Kernel 2: hactiv = tanh(y); write out+g_hact+g_hs4; head partial sums via
// atomics into g_head. 32 blocks x 128 threads (one j per thread).
// ---------------------------------------------------------------------------
__inline__ __device__ float warp_sum(float v) {
#pragma unroll
    for (int o = 16; o > 0; o >>= 1)
        v += __shfl_down_sync(0xffffffffu, v, o);
    return v;
}

__global__ void __launch_bounds__(128)
finalize_kernel(const float* __restrict__ Wo,
                const float* __restrict__ Wv,
                float* __restrict__ out) {
    int t = threadIdx.x;
    int j = blockIdx.x * 128 + t;
    float hact = tanhf(g_y[j]);
    out[OUT_HACT + j] = hact;
    g_hact[j] = hact;

    // shifted float4 view: g_hs4[m] = (hact[4m+3..4m+6]), m in [0,1022]
    int r = j & 3;
    if (r == 3) {                       // j = 4m+3, m <= 1022 when j <= 4091
        if (j <= 4091) g_hs4[(j - 3) >> 2].x = hact;
    } else if (r == 0) {                // j = 4m+4
        if (j >= 4)    g_hs4[(j - 4) >> 2].y = hact;
    } else if (r == 1) {                // j = 4m+5
        if (j >= 5)    g_hs4[(j - 5) >> 2].z = hact;
    } else {                            // j = 4m+6
        if (j >= 6)    g_hs4[(j - 6) >> 2].w = hact;
    }

    float4 wo = *(const float4*)(Wo + (size_t)j * 4);  // Wo[j][0..3]
    float p0 = hact * wo.x, p1 = hact * wo.y;
    float p2 = hact * wo.z, p3 = hact * wo.w;
    float pv = hact * Wv[j];

    __shared__ float sh[5][4];
    int lane = t & 31, wid = t >> 5;
    p0 = warp_sum(p0); p1 = warp_sum(p1); p2 = warp_sum(p2);
    p3 = warp_sum(p3); pv = warp_sum(pv);
    if (lane == 0) {
        sh[0][wid] = p0; sh[1][wid] = p1; sh[2][wid] = p2;
        sh[3][wid] = p3; sh[4][wid] = pv;
    }
    __syncthreads();
    if (t < 5) {
        float s = sh[t][0] + sh[t][1] + sh[t][2] + sh[t][3];
        atomicAdd(&g_head[t], s);
    }
}

// ---------------------------------------------------------------------------
// Kernel 3: hebb_new[i,j] = (1-eta)*hebb[i,j] + eta*hidden[i]*hactiv[j]
// R1-style grid-stride, compile-time 8 iterations (unroll 2 -> paired
// independent load batches). g_hs4 gives hact[j0..j0+3] in one LDG.128.
// Streaming stores keep the 64MB write from thrashing hebb's L2 lines.
// Block 0 thread 0 also emits softmax/value from g_head (finalize is done).
// ---------------------------------------------------------------------------
__global__ void __launch_bounds__(256)
hebb_update_kernel(const float* __restrict__ hebb,
                   const float* __restrict__ hidden,
                   const float* __restrict__ eta,
                   const float* __restrict__ bo,
                   const float* __restrict__ bv,
                   float* __restrict__ out) {
    const long long STRIDE = 2048LL * 256LL;   // 524288 threads, 8 chunks each
    long long tid = (long long)blockIdx.x * 256 + threadIdx.x;
    float et = __ldg(eta);
    float em = 1.0f - et;
    float* ho = out + OUT_HEBB;
    const float4* hb4 = (const float4*)hebb;

    if (blockIdx.x == 0 && threadIdx.x == 0) {
        // boundary elements: k = 0..2 (row 0) and k = HH-1 (row/col 4095)
#pragma unroll
        for (int k = 0; k < 3; k++)
            ho[k] = fmaf(em, hebb[k], et * hidden[0] * g_hact[k]);
        ho[HH - 1] = fmaf(em, hebb[HH - 1], et * hidden[H - 1] * g_hact[H - 1]);
        // heads: softmax(g_head[0..3] + bo), value = g_head[4] + bv
        float l0 = g_head[0] + bo[0], l1 = g_head[1] + bo[1];
        float l2 = g_head[2] + bo[2], l3 = g_head[3] + bo[3];
        float m = fmaxf(fmaxf(l0, l1), fmaxf(l2, l3));
        float e0 = expf(l0 - m), e1 = expf(l1 - m);
        float e2 = expf(l2 - m), e3 = expf(l3 - m);
        float inv = 1.0f / (e0 + e1 + e2 + e3);
        out[OUT_ACT + 0] = e0 * inv;
        out[OUT_ACT + 1] = e1 * inv;
        out[OUT_ACT + 2] = e2 * inv;
        out[OUT_ACT + 3] = e3 * inv;
        out[OUT_VAL] = g_head[4] + bv[0];
    }

#pragma unroll 2
    for (int e = 0; e < 8; e++) {
        long long q = tid + (long long)e * STRIDE;
        if (q >= NC) break;                   // only the very last thread exits early
        float4 A = hb4[q];
        float4 B = hb4[q + 1];                // same/adjacent 128B line
        float s0 = A.w, s1 = B.x, s2 = B.y, s3 = B.z;

        long long k = 4 * q + 3;
        int i0 = (int)(k >> 12);
        int j0 = (int)(k & (H - 1));
        float4 r;
        if (j0 != H - 1) {
            // fast path: all 4 elements in the same hebb row
            float hi = __ldg(hidden + i0) * et;
            float4 g = g_hs4[j0 >> 2];        // hact[j0 .. j0+3], one LDG.128
            r.x = fmaf(em, s0, hi * g.x);
            r.y = fmaf(em, s1, hi * g.y);
            r.z = fmaf(em, s2, hi * g.z);
            r.w = fmaf(em, s3, hi * g.w);
        } else {
            // chunk straddles a row boundary (1 per 4096 chunks)
            float src[4] = {s0, s1, s2, s3};
            float rr[4];
#pragma unroll
            for (int u = 0; u < 4; u++) {
                long long kk = k + u;
                int i = (int)(kk >> 12);
                int jj = (int)(kk & (H - 1));
                rr[u] = fmaf(em, src[u], et * __ldg(hidden + i) * g_hact[jj]);
            }
            r = make_float4(rr[0], rr[1], rr[2], rr[3]);
        }
        __stcs((float4*)(ho + k), r);         // 16B-aligned streaming store
    }
}

// ---------------------------------------------------------------------------
// inputs: x, hidden, hebb, Wi, bi, w, alpha, eta, Wo, bo, Wv, bv
// output: activout[4] | valueout[1] | hactiv[4096] | hebb_new[H*H]
// ---------------------------------------------------------------------------
extern "C" void kernel_launch(void* const* d_in, const int* in_sizes, int n_in,
                              void* d_out, int out_size) {
    const float* x      = (const float*)d_in[0];
    const float* hidden = (const float*)d_in[1];
    const float* hebb   = (const float*)d_in[2];
    const float* Wi     = (const float*)d_in[3];
    const float* bi     = (const float*)d_in[4];
    const float* w      = (const float*)d_in[5];
    const float* alpha  = (const float*)d_in[6];
    const float* eta    = (const float*)d_in[7];
    const float* Wo     = (const float*)d_in[8];
    const float* bo     = (const float*)d_in[9];
    const float* Wv     = (const float*)d_in[10];
    const float* bv     = (const float*)d_in[11];
    float* out = (float*)d_out;

    init_y_kernel<<<H / 256, 256>>>(x, Wi, bi);
    gemv_acc_kernel<<<dim3(4, 256), 256>>>(hidden, w, alpha, hebb);
    finalize_kernel<<<32, 128>>>(Wo, Wv, out);
    hebb_update_kernel<<<2048, 256>>>(hebb, hidden, eta, bo, bv, out);
}